// round 5
// baseline (speedup 1.0000x reference)
#include <cuda_runtime.h>
#include <math.h>

#define NB 2
#define RR 360
#define NN 100
#define SS 200
#define KXN 101
#define NPIX (NN*NN)
#define NLIG (NB*RR*2)
#define NIMG (NLIG + NB*2)
#define GPITCH 102

// ---------------- scratch (device globals; no allocation allowed) ----------
__device__ float  d_h1[4][9][NPIX];
__device__ float  d_feat[4][2][NPIX];            // 0..1 receptor b, 2..3 ligand b
__device__ float2 d_G[NIMG][NN][GPITCH];         // row DFT: [img][y][kx]
__device__ float2 d_F[NIMG][KXN][SS];            // fwd spectrum: [img][kx][ky]
__device__ float2 d_H[NB*RR][KXN][SS];           // after inv-ky: [imgH][kx][y]
__device__ unsigned int d_best[NB];
__device__ float  d_pos[NB];

__device__ __forceinline__ unsigned fenc(float f) {
    unsigned u = __float_as_uint(f);
    return (u & 0x80000000u) ? ~u : (u | 0x80000000u);
}
__device__ __forceinline__ float fdec(unsigned e) {
    unsigned u = (e & 0x80000000u) ? (e & 0x7FFFFFFFu) : ~e;
    return __uint_as_float(u);
}

__global__ void k_init() {
    int t = threadIdx.x;
    if (t < NB) { d_best[t] = 0u; d_pos[t] = 0.0f; }
}

// ---------------- conv1 + norm_relu (FIELDS1) -------------------------------
__global__ void k_conv1(const float* __restrict__ rec, const float* __restrict__ lig,
                        const float* __restrict__ w1) {
    int img = blockIdx.y;
    int p = blockIdx.x * blockDim.x + threadIdx.x;
    if (p >= NPIX) return;
    int y = p / NN, x = p % NN;
    const float* src = (img < NB) ? (rec + img * NPIX) : (lig + (img - NB) * NPIX);
    float acc[9];
#pragma unroll
    for (int o = 0; o < 9; o++) acc[o] = 0.0f;
#pragma unroll
    for (int ky = 0; ky < 5; ky++) {
        int iy = y + ky - 2;
        if ((unsigned)iy >= NN) continue;
#pragma unroll
        for (int kx = 0; kx < 5; kx++) {
            int ix = x + kx - 2;
            if ((unsigned)ix >= NN) continue;
            float v = __ldg(src + iy * NN + ix);
#pragma unroll
            for (int o = 0; o < 9; o++)
                acc[o] = fmaf(v, __ldg(w1 + o * 25 + ky * 5 + kx), acc[o]);
        }
    }
    {
        float a = acc[0];
        float n = sqrtf(a * a + 1e-12f);
        d_h1[img][0][p] = a * (n / (n + 1e-12f));
    }
#pragma unroll
    for (int g = 0; g < 4; g++) {
        int s = 1 + 2 * g;
        float a = acc[s], b = acc[s + 1];
        float n = sqrtf(a * a + b * b + 1e-12f);
        float sc = n / (n + 1e-12f);
        d_h1[img][s][p] = a * sc;
        d_h1[img][s + 1][p] = b * sc;
    }
}

// ---------------- conv2 + norm_relu (FIELDS2) + features --------------------
__global__ void k_conv2(const float* __restrict__ w2) {
    int img = blockIdx.y;
    int p = blockIdx.x * blockDim.x + threadIdx.x;
    if (p >= NPIX) return;
    int y = p / NN, x = p % NN;
    float acc[3] = {0.f, 0.f, 0.f};
    for (int ci = 0; ci < 9; ci++) {
        const float* hp = d_h1[img][ci];
#pragma unroll
        for (int ky = 0; ky < 5; ky++) {
            int iy = y + ky - 2;
            if ((unsigned)iy >= NN) continue;
#pragma unroll
            for (int kx = 0; kx < 5; kx++) {
                int ix = x + kx - 2;
                if ((unsigned)ix >= NN) continue;
                float v = hp[iy * NN + ix];
#pragma unroll
                for (int o = 0; o < 3; o++)
                    acc[o] = fmaf(v, __ldg(w2 + ((o * 9 + ci) * 5 + ky) * 5 + kx), acc[o]);
            }
        }
    }
    float o0, o1, o2;
    {
        float a = acc[0];
        float n = sqrtf(a * a + 1e-12f);
        o0 = a * (n / (n + 1e-12f));
    }
    {
        float a = acc[1], b = acc[2];
        float n = sqrtf(a * a + b * b + 1e-12f);
        float sc = n / (n + 1e-12f);
        o1 = a * sc; o2 = b * sc;
    }
    d_feat[img][0][p] = fabsf(o0);
    d_feat[img][1][p] = sqrtf(o1 * o1 + o2 * o2 + 1e-12f);
}

__device__ __forceinline__ float samp(const float* __restrict__ im, float yf, float xf) {
    if (yf < 0.f || yf >= 100.f || xf < 0.f || xf >= 100.f) return 0.f;
    int yc = (int)yf, xc = (int)xf;
    return im[yc * NN + xc];
}

// ---------------- rotate (fused) + row DFT ----------------------------------
// One block per image. Output d_G[img][y][kx] = sum_x rot[y][x] e^{-2pi i kx x/200}
__global__ void __launch_bounds__(256) k_rot_rowdft() {
    __shared__ __align__(16) float rotT[NN * 104];   // [x][y], pitch 104
    int bid = blockIdx.x;
    int tid = threadIdx.x;
    const float* src;
    bool ident;
    float ct = 1.f, st = 0.f;
    if (bid < NLIG) {
        int c = bid & 1;
        int r = (bid >> 1) % RR;
        int b = bid / (2 * RR);
        src = d_feat[NB + b][c];
        double th = -3.14159265358979323846 + (double)r * (6.283185307179586477 / 360.0);
        ct = (float)cos(th); st = (float)sin(th);
        ident = false;
    } else {
        int i = bid - NLIG;
        src = d_feat[i >> 1][i & 1];
        ident = true;
    }
    for (int p = tid; p < NPIX; p += blockDim.x) {
        int i = p / NN, j = p % NN;
        float val;
        if (ident) {
            val = src[p];
        } else {
            float xs = (float)j - 49.5f, ys = (float)i - 49.5f;
            float xq = ct * xs + st * ys + 49.5f;
            float yq = -st * xs + ct * ys + 49.5f;
            float x0f = floorf(xq), y0f = floorf(yq);
            float wx = xq - x0f, wy = yq - y0f;
            val = samp(src, y0f, x0f) * (1.f - wy) * (1.f - wx)
                + samp(src, y0f, x0f + 1.f) * (1.f - wy) * wx
                + samp(src, y0f + 1.f, x0f) * wy * (1.f - wx)
                + samp(src, y0f + 1.f, x0f + 1.f) * wy * wx;
        }
        rotT[j * 104 + i] = val;   // transposed store
    }
    __syncthreads();
    // tasks: (yb 0..4 of 20 y, kx 0..100); kx fastest -> lanes broadcast rotT
    for (int task = tid; task < 5 * KXN; task += 256) {
        int kx = task % KXN;
        int y0 = (task / KXN) * 20;
        double ang = -6.283185307179586477 * (double)kx / 200.0;
        double sr = cos(ang), si = sin(ang);
        double wr = 1.0, wi = 0.0;
        float aR[20], aI[20];
#pragma unroll
        for (int i = 0; i < 20; i++) { aR[i] = 0.f; aI[i] = 0.f; }
        for (int x = 0; x < NN; x++) {
            float wrf = (float)wr, wif = (float)wi;
            const float4* rp = reinterpret_cast<const float4*>(&rotT[x * 104 + y0]);
#pragma unroll
            for (int q = 0; q < 5; q++) {
                float4 v = rp[q];
                aR[q*4+0] = fmaf(v.x, wrf, aR[q*4+0]); aI[q*4+0] = fmaf(v.x, wif, aI[q*4+0]);
                aR[q*4+1] = fmaf(v.y, wrf, aR[q*4+1]); aI[q*4+1] = fmaf(v.y, wif, aI[q*4+1]);
                aR[q*4+2] = fmaf(v.z, wrf, aR[q*4+2]); aI[q*4+2] = fmaf(v.z, wif, aI[q*4+2]);
                aR[q*4+3] = fmaf(v.w, wrf, aR[q*4+3]); aI[q*4+3] = fmaf(v.w, wif, aI[q*4+3]);
            }
            double nr = fma(wr, sr, -wi * si);
            double ni = fma(wr, si, wi * sr);
            wr = nr; wi = ni;
        }
#pragma unroll
        for (int i = 0; i < 20; i++)
            d_G[bid][y0 + i][kx] = make_float2(aR[i], aI[i]);
    }
}

// ---------------- column DFT with radix-2 input split -----------------------
// F[u][kx] = A + t_u B ; F[u+100][kx] = A - t_u B ; t_u = e^{-i pi u/100}
// A = sum_v G[2v] e^{-2pi i u v/100}, B = sum_v G[2v+1] e^{-2pi i u v/100}
__global__ void __launch_bounds__(256) k_coldft() {
    __shared__ __align__(16) float2 GT[NN][56];   // [y][kx-local]
    int img = blockIdx.x >> 1;
    int half = blockIdx.x & 1;
    int kxg0 = half * 52;
    int width = half ? 49 : 52;
    int tid = threadIdx.x;
    for (int t = tid; t < NN * 56; t += 256) {
        int y = t / 56, kxl = t % 56;
        GT[y][kxl] = (kxl < width) ? d_G[img][y][kxg0 + kxl] : make_float2(0.f, 0.f);
    }
    __syncthreads();
    // tasks: u fastest (lanes share kxb -> broadcast loads, coalesced stores)
    for (int task = tid; task < 700; task += 256) {
        int u = task % 100;
        int kxl0 = (task / 100) * 8;
        double ang = -6.283185307179586477 * (double)u / 100.0;
        double sr = cos(ang), si = sin(ang);
        double wr = 1.0, wi = 0.0;
        float Ar[8], Ai[8], Br[8], Bi[8];
#pragma unroll
        for (int j = 0; j < 8; j++) { Ar[j]=Ai[j]=Br[j]=Bi[j]=0.f; }
        for (int v = 0; v < 50; v++) {
            float wrf = (float)wr, wif = (float)wi;
            const float4* pe = reinterpret_cast<const float4*>(&GT[2*v][kxl0]);
            const float4* po = reinterpret_cast<const float4*>(&GT[2*v+1][kxl0]);
#pragma unroll
            for (int q = 0; q < 4; q++) {
                float4 e = pe[q];
                Ar[2*q]   = fmaf(e.x, wrf, Ar[2*q]);   Ar[2*q]   = fmaf(-e.y, wif, Ar[2*q]);
                Ai[2*q]   = fmaf(e.x, wif, Ai[2*q]);   Ai[2*q]   = fmaf( e.y, wrf, Ai[2*q]);
                Ar[2*q+1] = fmaf(e.z, wrf, Ar[2*q+1]); Ar[2*q+1] = fmaf(-e.w, wif, Ar[2*q+1]);
                Ai[2*q+1] = fmaf(e.z, wif, Ai[2*q+1]); Ai[2*q+1] = fmaf( e.w, wrf, Ai[2*q+1]);
                float4 o = po[q];
                Br[2*q]   = fmaf(o.x, wrf, Br[2*q]);   Br[2*q]   = fmaf(-o.y, wif, Br[2*q]);
                Bi[2*q]   = fmaf(o.x, wif, Bi[2*q]);   Bi[2*q]   = fmaf( o.y, wrf, Bi[2*q]);
                Br[2*q+1] = fmaf(o.z, wrf, Br[2*q+1]); Br[2*q+1] = fmaf(-o.w, wif, Br[2*q+1]);
                Bi[2*q+1] = fmaf(o.z, wif, Bi[2*q+1]); Bi[2*q+1] = fmaf( o.w, wrf, Bi[2*q+1]);
            }
            double nr = fma(wr, sr, -wi * si);
            double ni = fma(wr, si, wi * sr);
            wr = nr; wi = ni;
        }
        double at = -3.14159265358979323846 * (double)u / 100.0;
        float tr = (float)cos(at), ti = (float)sin(at);
#pragma unroll
        for (int j = 0; j < 8; j++) {
            int kxl = kxl0 + j;
            if (kxl >= width) continue;          // FIX: guard on LOCAL width (was kx>100; raced across halves)
            int kx = kxg0 + kxl;
            float tbr = tr * Br[j] - ti * Bi[j];
            float tbi = tr * Bi[j] + ti * Br[j];
            d_F[img][kx][u]       = make_float2(Ar[j] + tbr, Ai[j] + tbi);
            d_F[img][kx][u + 100] = make_float2(Ar[j] - tbr, Ai[j] - tbi);
        }
    }
}

// ---------------- combine spectra + inverse ky (radix-2 output split) -------
// H[u][kx] = P + t_u Q ; H[u+100][kx] = P - t_u Q ; t_u = e^{+i pi u/100}
// P = sum_m sf[2m] e^{2pi i m u/100}, Q = sum_m sf[2m+1] e^{2pi i m u/100}
__global__ void __launch_bounds__(320) k_combine_invy(const float* __restrict__ wb,
        const float* __restrict__ wc1, const float* __restrict__ wc2,
        const float* __restrict__ wk) {
    __shared__ __align__(16) float2 sfs[SS][24];
    int chunk = blockIdx.x % 5;
    int imgH = blockIdx.x / 5;
    int b = imgH / RR;
    int kxg0 = chunk * 24;
    int width = (KXN - kxg0 < 24) ? (KXN - kxg0) : 24;
    int tid = threadIdx.x;
    float w0 = *wb, w1v = *wc1, w2v = *wc2, w3 = *wk;
    int imgL0 = imgH * 2, imgL1 = imgL0 + 1;
    int imgR0 = NLIG + b * 2, imgR1 = imgR0 + 1;
    for (int e = tid; e < SS * 24; e += 320) {
        int ky = e % SS, kxl = e / SS;
        float2 v = make_float2(0.f, 0.f);
        if (kxl < width) {
            int kx = kxg0 + kxl;
            float2 lb = d_F[imgL0][kx][ky];
            float2 lB = d_F[imgL1][kx][ky];
            float2 rb = d_F[imgR0][kx][ky];
            float2 rB = d_F[imgR1][kx][ky];
            float ur = w0 * lb.x + w1v * lB.x, ui = w0 * lb.y + w1v * lB.y;
            float vr = w2v * lb.x - w3 * lB.x, vi = w2v * lb.y - w3 * lB.y;
            v.x = rb.x * ur + rb.y * ui + rB.x * vr + rB.y * vi;
            v.y = rb.x * ui - rb.y * ur + rB.x * vi - rB.y * vr;
        }
        sfs[ky][kxl] = v;
    }
    __syncthreads();
    for (int task = tid; task < 300; task += 320) {
        int u = task % 100;
        int kxl0 = (task / 100) * 8;
        double ang = 6.283185307179586477 * (double)u / 100.0;
        double sr = cos(ang), si = sin(ang);
        double wr = 1.0, wi = 0.0;
        float Pr[8], Pi[8], Qr[8], Qi[8];
#pragma unroll
        for (int j = 0; j < 8; j++) { Pr[j]=Pi[j]=Qr[j]=Qi[j]=0.f; }
        for (int m = 0; m < 100; m++) {
            float wrf = (float)wr, wif = (float)wi;
            const float4* pe = reinterpret_cast<const float4*>(&sfs[2*m][kxl0]);
            const float4* po = reinterpret_cast<const float4*>(&sfs[2*m+1][kxl0]);
#pragma unroll
            for (int q = 0; q < 4; q++) {
                float4 e = pe[q];
                Pr[2*q]   = fmaf(e.x, wrf, Pr[2*q]);   Pr[2*q]   = fmaf(-e.y, wif, Pr[2*q]);
                Pi[2*q]   = fmaf(e.x, wif, Pi[2*q]);   Pi[2*q]   = fmaf( e.y, wrf, Pi[2*q]);
                Pr[2*q+1] = fmaf(e.z, wrf, Pr[2*q+1]); Pr[2*q+1] = fmaf(-e.w, wif, Pr[2*q+1]);
                Pi[2*q+1] = fmaf(e.z, wif, Pi[2*q+1]); Pi[2*q+1] = fmaf( e.w, wrf, Pi[2*q+1]);
                float4 o = po[q];
                Qr[2*q]   = fmaf(o.x, wrf, Qr[2*q]);   Qr[2*q]   = fmaf(-o.y, wif, Qr[2*q]);
                Qi[2*q]   = fmaf(o.x, wif, Qi[2*q]);   Qi[2*q]   = fmaf( o.y, wrf, Qi[2*q]);
                Qr[2*q+1] = fmaf(o.z, wrf, Qr[2*q+1]); Qr[2*q+1] = fmaf(-o.w, wif, Qr[2*q+1]);
                Qi[2*q+1] = fmaf(o.z, wif, Qi[2*q+1]); Qi[2*q+1] = fmaf( o.w, wrf, Qi[2*q+1]);
            }
            double nr = fma(wr, sr, -wi * si);
            double ni = fma(wr, si, wi * sr);
            wr = nr; wi = ni;
        }
        double at = 3.14159265358979323846 * (double)u / 100.0;
        float tr = (float)cos(at), ti = (float)sin(at);
#pragma unroll
        for (int j = 0; j < 8; j++) {
            int kxl = kxl0 + j;
            if (kxl >= width) continue;          // guard on local width (chunk-exclusive columns)
            int kx = kxg0 + kxl;
            float tqr = tr * Qr[j] - ti * Qi[j];
            float tqi = tr * Qi[j] + ti * Qr[j];
            d_H[imgH][kx][u]       = make_float2(Pr[j] + tqr, Pi[j] + tqi);
            d_H[imgH][kx][u + 100] = make_float2(Pr[j] - tqr, Pi[j] - tqi);
        }
    }
}

// ---------------- inverse kx (real, radix-2 output split) + reduce ----------
// s[y][u]     = E + 2 Re(t_u C),  s[y][u+100] = E - 2 Re(t_u C)
// E = Hr0 + (-1)^u Hr100 + sum_{m=1..49} 2 Re(H[2m] w_m)
// C = sum_{m=0..49} H[2m+1] w_m,   w_m = e^{2pi i m u/100}, t_u = e^{i pi u/100}
__global__ void __launch_bounds__(256) k_invx_reduce(const int* __restrict__ gtr,
                                                     const int* __restrict__ gtt) {
    __shared__ __align__(16) float2 HT[KXN][20];
    __shared__ float red[256];
    int yc = blockIdx.x % 10;
    int imgH = blockIdx.x / 10;
    int b = imgH / RR, r = imgH % RR;
    int ybase = yc * 20;
    int tid = threadIdx.x;
    for (int e = tid; e < KXN * 20; e += 256) {
        int kx = e / 20, yl = e % 20;
        HT[kx][yl] = d_H[imgH][kx][ybase + yl];
    }
    __syncthreads();
    int gr = gtr[b], t0 = gtt[2 * b], t1 = gtt[2 * b + 1];
    const float inv = 1.0f / 40000.0f;
    float lmax = -3.4e38f;
    for (int task = tid; task < 200; task += 256) {
        int u = task % 100;
        int y0 = (task / 100) * 10;
        double ang = 6.283185307179586477 * (double)u / 100.0;
        double sr = cos(ang), si = sin(ang);
        double wr = 1.0, wi = 0.0;
        float E[10], Cr[10], Ci[10];
        float sgn = (u & 1) ? -1.f : 1.f;
#pragma unroll
        for (int i = 0; i < 10; i++) {
            E[i]  = HT[0][y0 + i].x + sgn * HT[100][y0 + i].x;
            Cr[i] = HT[1][y0 + i].x;
            Ci[i] = HT[1][y0 + i].y;
        }
        for (int m = 1; m < 50; m++) {
            double nr = fma(wr, sr, -wi * si);
            double ni = fma(wr, si, wi * sr);
            wr = nr; wi = ni;
            float wrf = (float)wr, wif = (float)wi;
            float w2r = 2.f * wrf, w2i = 2.f * wif;
            const float4* pe = reinterpret_cast<const float4*>(&HT[2*m][y0]);
            const float4* po = reinterpret_cast<const float4*>(&HT[2*m+1][y0]);
#pragma unroll
            for (int q = 0; q < 5; q++) {
                float4 e = pe[q];
                E[2*q]   = fmaf(e.x, w2r, E[2*q]);   E[2*q]   = fmaf(-e.y, w2i, E[2*q]);
                E[2*q+1] = fmaf(e.z, w2r, E[2*q+1]); E[2*q+1] = fmaf(-e.w, w2i, E[2*q+1]);
                float4 o = po[q];
                Cr[2*q]   = fmaf(o.x, wrf, Cr[2*q]);   Cr[2*q]   = fmaf(-o.y, wif, Cr[2*q]);
                Ci[2*q]   = fmaf(o.x, wif, Ci[2*q]);   Ci[2*q]   = fmaf( o.y, wrf, Ci[2*q]);
                Cr[2*q+1] = fmaf(o.z, wrf, Cr[2*q+1]); Cr[2*q+1] = fmaf(-o.w, wif, Cr[2*q+1]);
                Ci[2*q+1] = fmaf(o.z, wif, Ci[2*q+1]); Ci[2*q+1] = fmaf( o.w, wrf, Ci[2*q+1]);
            }
        }
        double at = 3.14159265358979323846 * (double)u / 100.0;
        float tr = (float)cos(at), ti = (float)sin(at);
#pragma unroll
        for (int i = 0; i < 10; i++) {
            float oc = 2.f * (Cr[i] * tr - Ci[i] * ti);
            float s0 = (E[i] + oc) * inv;
            float s1 = (E[i] - oc) * inv;
            lmax = fmaxf(lmax, fmaxf(s0, s1));
            int y = ybase + y0 + i;
            if (r == gr && y == t0) {
                if (u == t1) d_pos[b] = s0;
                if (u + 100 == t1) d_pos[b] = s1;
            }
        }
    }
    red[tid] = lmax;
    __syncthreads();
    for (int s2 = 128; s2 > 0; s2 >>= 1) {
        if (tid < s2) red[tid] = fmaxf(red[tid], red[tid + s2]);
        __syncthreads();
    }
    if (tid == 0) atomicMax(&d_best[b], fenc(red[0]));
}

__global__ void k_final(float* __restrict__ out) {
    if (threadIdx.x == 0) {
        float lp = 0.f, ln = 0.f;
        for (int b = 0; b < NB; b++) {
            float p = d_pos[b];
            lp += p + p * p;
            float m = fdec(d_best[b]);
            ln += -m + m * m;
        }
        out[0] = lp / (float)NB;
        out[1] = ln / (float)NB;
    }
}

extern "C" void kernel_launch(void* const* d_in, const int* in_sizes, int n_in,
                              void* d_out, int out_size) {
    const float* rec = (const float*)d_in[0];
    const float* lig = (const float*)d_in[1];
    const float* w1 = (const float*)d_in[2];
    const float* w2 = (const float*)d_in[3];
    const float* wb = (const float*)d_in[4];
    const float* wc1 = (const float*)d_in[5];
    const float* wc2 = (const float*)d_in[6];
    const float* wk = (const float*)d_in[7];
    const int* gtr = (const int*)d_in[8];
    const int* gtt = (const int*)d_in[9];
    float* out = (float*)d_out;

    k_init<<<1, 32>>>();
    dim3 gconv((NPIX + 255) / 256, 4);
    k_conv1<<<gconv, 256>>>(rec, lig, w1);
    k_conv2<<<gconv, 256>>>(w2);
    k_rot_rowdft<<<NIMG, 256>>>();
    k_coldft<<<NIMG * 2, 256>>>();
    k_combine_invy<<<NB * RR * 5, 320>>>(wb, wc1, wc2, wk);
    k_invx_reduce<<<NB * RR * 10, 256>>>(gtr, gtt);
    k_final<<<1, 32>>>(out);
}

// round 6
// speedup vs baseline: 4.1191x; 4.1191x over previous
#include <cuda_runtime.h>
#include <math.h>

#define NB 2
#define RR 360
#define NN 100
#define SS 200
#define KXN 101
#define NPIX (NN*NN)
#define NLIG (NB*RR*2)
#define NIMG (NLIG + NB*2)
#define GPITCH 102

// ---------------- scratch (device globals; no allocation allowed) ----------
__device__ float  d_h1[4][9][NPIX];
__device__ float  d_feat[4][2][NPIX];            // 0..1 receptor b, 2..3 ligand b
__device__ float2 d_G[NIMG][NN][GPITCH];         // row DFT: [img][y][kx]
__device__ float2 d_F[NIMG][KXN][SS];            // fwd spectrum: [img][kx][ky]
__device__ float2 d_H[NB*RR][KXN][SS];           // after inv-ky: [imgH][kx][y]
__device__ unsigned int d_best[NB];
__device__ float  d_pos[NB];

// e^{i pi j/4}: cos, sin tables (exact-to-eps reseed points)
__device__ __constant__ float C8[8] = {1.f, 0.70710678118654752f, 0.f, -0.70710678118654752f,
                                       -1.f, -0.70710678118654752f, 0.f, 0.70710678118654752f};
__device__ __constant__ float S8[8] = {0.f, 0.70710678118654752f, 1.f, 0.70710678118654752f,
                                       0.f, -0.70710678118654752f, -1.f, -0.70710678118654752f};

__device__ __forceinline__ unsigned fenc(float f) {
    unsigned u = __float_as_uint(f);
    return (u & 0x80000000u) ? ~u : (u | 0x80000000u);
}
__device__ __forceinline__ float fdec(unsigned e) {
    unsigned u = (e & 0x80000000u) ? (e & 0x7FFFFFFFu) : ~e;
    return __uint_as_float(u);
}

__global__ void k_init() {
    int t = threadIdx.x;
    if (t < NB) { d_best[t] = 0u; d_pos[t] = 0.0f; }
}

// ---------------- conv1 + norm_relu (FIELDS1) -------------------------------
__global__ void k_conv1(const float* __restrict__ rec, const float* __restrict__ lig,
                        const float* __restrict__ w1) {
    int img = blockIdx.y;
    int p = blockIdx.x * blockDim.x + threadIdx.x;
    if (p >= NPIX) return;
    int y = p / NN, x = p % NN;
    const float* src = (img < NB) ? (rec + img * NPIX) : (lig + (img - NB) * NPIX);
    float acc[9];
#pragma unroll
    for (int o = 0; o < 9; o++) acc[o] = 0.0f;
#pragma unroll
    for (int ky = 0; ky < 5; ky++) {
        int iy = y + ky - 2;
        if ((unsigned)iy >= NN) continue;
#pragma unroll
        for (int kx = 0; kx < 5; kx++) {
            int ix = x + kx - 2;
            if ((unsigned)ix >= NN) continue;
            float v = __ldg(src + iy * NN + ix);
#pragma unroll
            for (int o = 0; o < 9; o++)
                acc[o] = fmaf(v, __ldg(w1 + o * 25 + ky * 5 + kx), acc[o]);
        }
    }
    {
        float a = acc[0];
        float n = sqrtf(a * a + 1e-12f);
        d_h1[img][0][p] = a * (n / (n + 1e-12f));
    }
#pragma unroll
    for (int g = 0; g < 4; g++) {
        int s = 1 + 2 * g;
        float a = acc[s], b = acc[s + 1];
        float n = sqrtf(a * a + b * b + 1e-12f);
        float sc = n / (n + 1e-12f);
        d_h1[img][s][p] = a * sc;
        d_h1[img][s + 1][p] = b * sc;
    }
}

// ---------------- conv2 + norm_relu (FIELDS2) + features --------------------
__global__ void k_conv2(const float* __restrict__ w2) {
    int img = blockIdx.y;
    int p = blockIdx.x * blockDim.x + threadIdx.x;
    if (p >= NPIX) return;
    int y = p / NN, x = p % NN;
    float acc[3] = {0.f, 0.f, 0.f};
    for (int ci = 0; ci < 9; ci++) {
        const float* hp = d_h1[img][ci];
#pragma unroll
        for (int ky = 0; ky < 5; ky++) {
            int iy = y + ky - 2;
            if ((unsigned)iy >= NN) continue;
#pragma unroll
            for (int kx = 0; kx < 5; kx++) {
                int ix = x + kx - 2;
                if ((unsigned)ix >= NN) continue;
                float v = hp[iy * NN + ix];
#pragma unroll
                for (int o = 0; o < 3; o++)
                    acc[o] = fmaf(v, __ldg(w2 + ((o * 9 + ci) * 5 + ky) * 5 + kx), acc[o]);
            }
        }
    }
    float o0, o1, o2;
    {
        float a = acc[0];
        float n = sqrtf(a * a + 1e-12f);
        o0 = a * (n / (n + 1e-12f));
    }
    {
        float a = acc[1], b = acc[2];
        float n = sqrtf(a * a + b * b + 1e-12f);
        float sc = n / (n + 1e-12f);
        o1 = a * sc; o2 = b * sc;
    }
    d_feat[img][0][p] = fabsf(o0);
    d_feat[img][1][p] = sqrtf(o1 * o1 + o2 * o2 + 1e-12f);
}

__device__ __forceinline__ float samp(const float* __restrict__ im, float yf, float xf) {
    if (yf < 0.f || yf >= 100.f || xf < 0.f || xf >= 100.f) return 0.f;
    int yc = (int)yf, xc = (int)xf;
    return im[yc * NN + xc];
}

// ---------------- rotate (fused) + row DFT ----------------------------------
// One block per image. Output d_G[img][y][kx] = sum_x rot[y][x] e^{-2pi i kx x/200}
__global__ void __launch_bounds__(256) k_rot_rowdft() {
    __shared__ __align__(16) float rotT[NN * 104];   // [x][y], pitch 104
    int bid = blockIdx.x;
    int tid = threadIdx.x;
    const float* src;
    bool ident;
    float ct = 1.f, st = 0.f;
    if (bid < NLIG) {
        int c = bid & 1;
        int r = (bid >> 1) % RR;
        int b = bid / (2 * RR);
        src = d_feat[NB + b][c];
        double th = -3.14159265358979323846 + (double)r * (6.283185307179586477 / 360.0);
        ct = (float)cos(th); st = (float)sin(th);
        ident = false;
    } else {
        int i = bid - NLIG;
        src = d_feat[i >> 1][i & 1];
        ident = true;
    }
    for (int p = tid; p < NPIX; p += blockDim.x) {
        int i = p / NN, j = p % NN;
        float val;
        if (ident) {
            val = src[p];
        } else {
            float xs = (float)j - 49.5f, ys = (float)i - 49.5f;
            float xq = ct * xs + st * ys + 49.5f;
            float yq = -st * xs + ct * ys + 49.5f;
            float x0f = floorf(xq), y0f = floorf(yq);
            float wx = xq - x0f, wy = yq - y0f;
            val = samp(src, y0f, x0f) * (1.f - wy) * (1.f - wx)
                + samp(src, y0f, x0f + 1.f) * (1.f - wy) * wx
                + samp(src, y0f + 1.f, x0f) * wy * (1.f - wx)
                + samp(src, y0f + 1.f, x0f + 1.f) * wy * wx;
        }
        rotT[j * 104 + i] = val;   // transposed store
    }
    __syncthreads();
    // tasks: (yb 0..4 of 20 y, kx 0..100); kx fastest -> lanes broadcast rotT
    for (int task = tid; task < 5 * KXN; task += 256) {
        int kx = task % KXN;
        int y0 = (task / KXN) * 20;
        float sif, srf;
        sincosf(-3.14159265358979f * (float)kx * 0.01f, &sif, &srf);  // step e^{-i pi kx/100}
        float wr = 1.f, wi = 0.f;
        float aR[20], aI[20];
#pragma unroll
        for (int i = 0; i < 20; i++) { aR[i] = 0.f; aI[i] = 0.f; }
        for (int x = 0; x < NN; x++) {
            if ((x & 24) && (x % 25 == 0)) {      // x = 25, 50, 75: exact reseed
                int j = (kx * (x / 25)) & 7;      // phase = -pi*j/4
                wr = C8[j]; wi = -S8[j];
            }
            const float4* rp = reinterpret_cast<const float4*>(&rotT[x * 104 + y0]);
#pragma unroll
            for (int q = 0; q < 5; q++) {
                float4 v = rp[q];
                aR[q*4+0] = fmaf(v.x, wr, aR[q*4+0]); aI[q*4+0] = fmaf(v.x, wi, aI[q*4+0]);
                aR[q*4+1] = fmaf(v.y, wr, aR[q*4+1]); aI[q*4+1] = fmaf(v.y, wi, aI[q*4+1]);
                aR[q*4+2] = fmaf(v.z, wr, aR[q*4+2]); aI[q*4+2] = fmaf(v.z, wi, aI[q*4+2]);
                aR[q*4+3] = fmaf(v.w, wr, aR[q*4+3]); aI[q*4+3] = fmaf(v.w, wi, aI[q*4+3]);
            }
            float nr = fmaf(wr, srf, -wi * sif);
            float ni = fmaf(wr, sif, wi * srf);
            wr = nr; wi = ni;
        }
#pragma unroll
        for (int i = 0; i < 20; i++)
            d_G[bid][y0 + i][kx] = make_float2(aR[i], aI[i]);
    }
}

// ---------------- column DFT with radix-2 input split -----------------------
// F[u][kx] = A + t_u B ; F[u+100][kx] = A - t_u B ; t_u = e^{-i pi u/100}
__global__ void __launch_bounds__(256) k_coldft() {
    __shared__ __align__(16) float2 GT[NN][56];   // [y][kx-local]
    int img = blockIdx.x >> 1;
    int half = blockIdx.x & 1;
    int kxg0 = half * 52;
    int width = half ? 49 : 52;
    int tid = threadIdx.x;
    for (int t = tid; t < NN * 56; t += 256) {
        int y = t / 56, kxl = t % 56;
        GT[y][kxl] = (kxl < width) ? d_G[img][y][kxg0 + kxl] : make_float2(0.f, 0.f);
    }
    __syncthreads();
    for (int task = tid; task < 700; task += 256) {
        int u = task % 100;
        int kxl0 = (task / 100) * 8;
        int uw = (u > 50) ? u - 100 : u;           // wrap to halve |step angle|
        float sif, srf;
        sincosf(-6.28318530717959f * (float)uw * 0.01f, &sif, &srf);
        float wr = 1.f, wi = 0.f;
        float Ar[8], Ai[8], Br[8], Bi[8];
#pragma unroll
        for (int j = 0; j < 8; j++) { Ar[j]=Ai[j]=Br[j]=Bi[j]=0.f; }
        for (int v = 0; v < 50; v++) {
            if (v == 25) {                         // phase = -pi*u/2 exact
                int j = (2 * u) & 7;
                wr = C8[j]; wi = -S8[j];
            }
            const float4* pe = reinterpret_cast<const float4*>(&GT[2*v][kxl0]);
            const float4* po = reinterpret_cast<const float4*>(&GT[2*v+1][kxl0]);
#pragma unroll
            for (int q = 0; q < 4; q++) {
                float4 e = pe[q];
                Ar[2*q]   = fmaf(e.x, wr, Ar[2*q]);   Ar[2*q]   = fmaf(-e.y, wi, Ar[2*q]);
                Ai[2*q]   = fmaf(e.x, wi, Ai[2*q]);   Ai[2*q]   = fmaf( e.y, wr, Ai[2*q]);
                Ar[2*q+1] = fmaf(e.z, wr, Ar[2*q+1]); Ar[2*q+1] = fmaf(-e.w, wi, Ar[2*q+1]);
                Ai[2*q+1] = fmaf(e.z, wi, Ai[2*q+1]); Ai[2*q+1] = fmaf( e.w, wr, Ai[2*q+1]);
                float4 o = po[q];
                Br[2*q]   = fmaf(o.x, wr, Br[2*q]);   Br[2*q]   = fmaf(-o.y, wi, Br[2*q]);
                Bi[2*q]   = fmaf(o.x, wi, Bi[2*q]);   Bi[2*q]   = fmaf( o.y, wr, Bi[2*q]);
                Br[2*q+1] = fmaf(o.z, wr, Br[2*q+1]); Br[2*q+1] = fmaf(-o.w, wi, Br[2*q+1]);
                Bi[2*q+1] = fmaf(o.z, wi, Bi[2*q+1]); Bi[2*q+1] = fmaf( o.w, wr, Bi[2*q+1]);
            }
            float nr = fmaf(wr, srf, -wi * sif);
            float ni = fmaf(wr, sif, wi * srf);
            wr = nr; wi = ni;
        }
        float tr, ti;
        sincosf(-3.14159265358979f * (float)u * 0.01f, &ti, &tr);
#pragma unroll
        for (int j = 0; j < 8; j++) {
            int kxl = kxl0 + j;
            if (kxl >= width) continue;           // local-width guard (no cross-half race)
            int kx = kxg0 + kxl;
            float tbr = tr * Br[j] - ti * Bi[j];
            float tbi = tr * Bi[j] + ti * Br[j];
            d_F[img][kx][u]       = make_float2(Ar[j] + tbr, Ai[j] + tbi);
            d_F[img][kx][u + 100] = make_float2(Ar[j] - tbr, Ai[j] - tbi);
        }
    }
}

// ---------------- combine spectra + inverse ky (radix-2 output split) -------
// H[u][kx] = P + t_u Q ; H[u+100][kx] = P - t_u Q ; t_u = e^{+i pi u/100}
__global__ void __launch_bounds__(320) k_combine_invy(const float* __restrict__ wb,
        const float* __restrict__ wc1, const float* __restrict__ wc2,
        const float* __restrict__ wk) {
    __shared__ __align__(16) float2 sfs[SS][24];
    int chunk = blockIdx.x % 5;
    int imgH = blockIdx.x / 5;
    int b = imgH / RR;
    int kxg0 = chunk * 24;
    int width = (KXN - kxg0 < 24) ? (KXN - kxg0) : 24;
    int tid = threadIdx.x;
    float w0 = *wb, w1v = *wc1, w2v = *wc2, w3 = *wk;
    int imgL0 = imgH * 2, imgL1 = imgL0 + 1;
    int imgR0 = NLIG + b * 2, imgR1 = imgR0 + 1;
    for (int e = tid; e < SS * 24; e += 320) {
        int ky = e % SS, kxl = e / SS;
        float2 v = make_float2(0.f, 0.f);
        if (kxl < width) {
            int kx = kxg0 + kxl;
            float2 lb = d_F[imgL0][kx][ky];
            float2 lB = d_F[imgL1][kx][ky];
            float2 rb = d_F[imgR0][kx][ky];
            float2 rB = d_F[imgR1][kx][ky];
            float ur = w0 * lb.x + w1v * lB.x, ui = w0 * lb.y + w1v * lB.y;
            float vr = w2v * lb.x - w3 * lB.x, vi = w2v * lb.y - w3 * lB.y;
            v.x = rb.x * ur + rb.y * ui + rB.x * vr + rB.y * vi;
            v.y = rb.x * ui - rb.y * ur + rB.x * vi - rB.y * vr;
        }
        sfs[ky][kxl] = v;
    }
    __syncthreads();
    for (int task = tid; task < 300; task += 320) {
        int u = task % 100;
        int kxl0 = (task / 100) * 8;
        int uw = (u > 50) ? u - 100 : u;
        float sif, srf;
        sincosf(6.28318530717959f * (float)uw * 0.01f, &sif, &srf);
        float wr = 1.f, wi = 0.f;
        float Pr[8], Pi[8], Qr[8], Qi[8];
#pragma unroll
        for (int j = 0; j < 8; j++) { Pr[j]=Pi[j]=Qr[j]=Qi[j]=0.f; }
        for (int m = 0; m < 100; m++) {
            if ((m & 24) && (m % 25 == 0)) {       // m = 25,50,75: phase = +pi*u*(m/25)/2
                int j = (2 * u * (m / 25)) & 7;
                wr = C8[j]; wi = S8[j];
            }
            const float4* pe = reinterpret_cast<const float4*>(&sfs[2*m][kxl0]);
            const float4* po = reinterpret_cast<const float4*>(&sfs[2*m+1][kxl0]);
#pragma unroll
            for (int q = 0; q < 4; q++) {
                float4 e = pe[q];
                Pr[2*q]   = fmaf(e.x, wr, Pr[2*q]);   Pr[2*q]   = fmaf(-e.y, wi, Pr[2*q]);
                Pi[2*q]   = fmaf(e.x, wi, Pi[2*q]);   Pi[2*q]   = fmaf( e.y, wr, Pi[2*q]);
                Pr[2*q+1] = fmaf(e.z, wr, Pr[2*q+1]); Pr[2*q+1] = fmaf(-e.w, wi, Pr[2*q+1]);
                Pi[2*q+1] = fmaf(e.z, wi, Pi[2*q+1]); Pi[2*q+1] = fmaf( e.w, wr, Pi[2*q+1]);
                float4 o = po[q];
                Qr[2*q]   = fmaf(o.x, wr, Qr[2*q]);   Qr[2*q]   = fmaf(-o.y, wi, Qr[2*q]);
                Qi[2*q]   = fmaf(o.x, wi, Qi[2*q]);   Qi[2*q]   = fmaf( o.y, wr, Qi[2*q]);
                Qr[2*q+1] = fmaf(o.z, wr, Qr[2*q+1]); Qr[2*q+1] = fmaf(-o.w, wi, Qr[2*q+1]);
                Qi[2*q+1] = fmaf(o.z, wi, Qi[2*q+1]); Qi[2*q+1] = fmaf( o.w, wr, Qi[2*q+1]);
            }
            float nr = fmaf(wr, srf, -wi * sif);
            float ni = fmaf(wr, sif, wi * srf);
            wr = nr; wi = ni;
        }
        float tr, ti;
        sincosf(3.14159265358979f * (float)u * 0.01f, &ti, &tr);
#pragma unroll
        for (int j = 0; j < 8; j++) {
            int kxl = kxl0 + j;
            if (kxl >= width) continue;
            int kx = kxg0 + kxl;
            float tqr = tr * Qr[j] - ti * Qi[j];
            float tqi = tr * Qi[j] + ti * Qr[j];
            d_H[imgH][kx][u]       = make_float2(Pr[j] + tqr, Pi[j] + tqi);
            d_H[imgH][kx][u + 100] = make_float2(Pr[j] - tqr, Pi[j] - tqi);
        }
    }
}

// ---------------- inverse kx (real, radix-2 output split) + reduce ----------
__global__ void __launch_bounds__(256) k_invx_reduce(const int* __restrict__ gtr,
                                                     const int* __restrict__ gtt) {
    __shared__ __align__(16) float2 HT[KXN][20];
    __shared__ float red[256];
    int yc = blockIdx.x % 10;
    int imgH = blockIdx.x / 10;
    int b = imgH / RR, r = imgH % RR;
    int ybase = yc * 20;
    int tid = threadIdx.x;
    for (int e = tid; e < KXN * 20; e += 256) {
        int kx = e / 20, yl = e % 20;
        HT[kx][yl] = d_H[imgH][kx][ybase + yl];
    }
    __syncthreads();
    int gr = gtr[b], t0 = gtt[2 * b], t1 = gtt[2 * b + 1];
    const float inv = 1.0f / 40000.0f;
    float lmax = -3.4e38f;
    for (int task = tid; task < 200; task += 256) {
        int u = task % 100;
        int y0 = (task / 100) * 10;
        int uw = (u > 50) ? u - 100 : u;
        float sif, srf;
        sincosf(6.28318530717959f * (float)uw * 0.01f, &sif, &srf);
        float wr = 1.f, wi = 0.f;
        float E[10], Cr[10], Ci[10];
        float sgn = (u & 1) ? -1.f : 1.f;
#pragma unroll
        for (int i = 0; i < 10; i++) {
            E[i]  = HT[0][y0 + i].x + sgn * HT[100][y0 + i].x;
            Cr[i] = HT[1][y0 + i].x;
            Ci[i] = HT[1][y0 + i].y;
        }
        for (int m = 1; m < 50; m++) {
            float nr = fmaf(wr, srf, -wi * sif);
            float ni = fmaf(wr, sif, wi * srf);
            wr = nr; wi = ni;
            if (m == 25) {                         // phase = +pi*u/2 exact
                int j = (2 * u) & 7;
                wr = C8[j]; wi = S8[j];
            }
            float w2r = 2.f * wr, w2i = 2.f * wi;
            const float4* pe = reinterpret_cast<const float4*>(&HT[2*m][y0]);
            const float4* po = reinterpret_cast<const float4*>(&HT[2*m+1][y0]);
#pragma unroll
            for (int q = 0; q < 5; q++) {
                float4 e = pe[q];
                E[2*q]   = fmaf(e.x, w2r, E[2*q]);   E[2*q]   = fmaf(-e.y, w2i, E[2*q]);
                E[2*q+1] = fmaf(e.z, w2r, E[2*q+1]); E[2*q+1] = fmaf(-e.w, w2i, E[2*q+1]);
                float4 o = po[q];
                Cr[2*q]   = fmaf(o.x, wr, Cr[2*q]);   Cr[2*q]   = fmaf(-o.y, wi, Cr[2*q]);
                Ci[2*q]   = fmaf(o.x, wi, Ci[2*q]);   Ci[2*q]   = fmaf( o.y, wr, Ci[2*q]);
                Cr[2*q+1] = fmaf(o.z, wr, Cr[2*q+1]); Cr[2*q+1] = fmaf(-o.w, wi, Cr[2*q+1]);
                Ci[2*q+1] = fmaf(o.z, wi, Ci[2*q+1]); Ci[2*q+1] = fmaf( o.w, wr, Ci[2*q+1]);
            }
        }
        float tr, ti;
        sincosf(3.14159265358979f * (float)u * 0.01f, &ti, &tr);
#pragma unroll
        for (int i = 0; i < 10; i++) {
            float oc = 2.f * (Cr[i] * tr - Ci[i] * ti);
            float s0 = (E[i] + oc) * inv;
            float s1 = (E[i] - oc) * inv;
            lmax = fmaxf(lmax, fmaxf(s0, s1));
            int y = ybase + y0 + i;
            if (r == gr && y == t0) {
                if (u == t1) d_pos[b] = s0;
                if (u + 100 == t1) d_pos[b] = s1;
            }
        }
    }
    red[tid] = lmax;
    __syncthreads();
    for (int s2 = 128; s2 > 0; s2 >>= 1) {
        if (tid < s2) red[tid] = fmaxf(red[tid], red[tid + s2]);
        __syncthreads();
    }
    if (tid == 0) atomicMax(&d_best[b], fenc(red[0]));
}

__global__ void k_final(float* __restrict__ out) {
    if (threadIdx.x == 0) {
        float lp = 0.f, ln = 0.f;
        for (int b = 0; b < NB; b++) {
            float p = d_pos[b];
            lp += p + p * p;
            float m = fdec(d_best[b]);
            ln += -m + m * m;
        }
        out[0] = lp / (float)NB;
        out[1] = ln / (float)NB;
    }
}

extern "C" void kernel_launch(void* const* d_in, const int* in_sizes, int n_in,
                              void* d_out, int out_size) {
    const float* rec = (const float*)d_in[0];
    const float* lig = (const float*)d_in[1];
    const float* w1 = (const float*)d_in[2];
    const float* w2 = (const float*)d_in[3];
    const float* wb = (const float*)d_in[4];
    const float* wc1 = (const float*)d_in[5];
    const float* wc2 = (const float*)d_in[6];
    const float* wk = (const float*)d_in[7];
    const int* gtr = (const int*)d_in[8];
    const int* gtt = (const int*)d_in[9];
    float* out = (float*)d_out;

    k_init<<<1, 32>>>();
    dim3 gconv((NPIX + 255) / 256, 4);
    k_conv1<<<gconv, 256>>>(rec, lig, w1);
    k_conv2<<<gconv, 256>>>(w2);
    k_rot_rowdft<<<NIMG, 256>>>();
    k_coldft<<<NIMG * 2, 256>>>();
    k_combine_invy<<<NB * RR * 5, 320>>>(wb, wc1, wc2, wk);
    k_invx_reduce<<<NB * RR * 10, 256>>>(gtr, gtt);
    k_final<<<1, 32>>>(out);
}